// round 16
// baseline (speedup 1.0000x reference)
#include <cuda_runtime.h>
#include <stdint.h>

#define NN 100000
#define EE 1600000
#define DD 32
#define KTOP 1024
#define HBITS 17
#define HSIZE (1 << HBITS)
#define CAP 2048
#define TPB 256

// ---------------- scratch (device globals; no allocation allowed) ----------------
__device__ int    g_rowcnt[NN];
__device__ int    g_rowptr[NN + 1];
__device__ int    g_cursor[NN];
__device__ int    g_perm[EE];
__device__ int4   g_cve[EE];             // (col, val bits, eid, pad); compacted in-row per step
__device__ int    g_deg[NN];
__device__ float  g_e0[NN * DD], g_e1[NN * DD], g_e2[NN * DD];
__device__ float  g_n0[NN], g_n1[NN], g_n2[NN];
__device__ float  g_order[NN];
__device__ float  g_scores[NN];
__device__ int    g_hist[HSIZE];
__device__ int    g_blockTot[2048], g_blockOff[2048];
__device__ int    g_chunkSum[1024];
__device__ int    g_sel_digit;
__device__ int    g_cand_cnt;
__device__ unsigned int g_cand_key[CAP];
__device__ int    g_cand_idx[CAP];
// software grid barrier state (zero-init; generation monotonic across launches)
__device__ int    g_bar_count;
__device__ volatile unsigned g_bar_gen;

// ---------------- threefry2x32 (JAX-compatible, partitionable mode) ----------------
__host__ __device__ __forceinline__ void tf2x32(uint32_t k0, uint32_t k1,
                                                uint32_t x0, uint32_t x1,
                                                uint32_t &o0, uint32_t &o1) {
    uint32_t ks2 = k0 ^ k1 ^ 0x1BD11BDAu;
    x0 += k0; x1 += k1;
#define TFR(r) do { x0 += x1; x1 = (x1 << (r)) | (x1 >> (32 - (r))); x1 ^= x0; } while (0)
    TFR(13); TFR(15); TFR(26); TFR(6);
    x0 += k1;  x1 += ks2 + 1u;
    TFR(17); TFR(29); TFR(16); TFR(24);
    x0 += ks2; x1 += k0 + 2u;
    TFR(13); TFR(15); TFR(26); TFR(6);
    x0 += k0;  x1 += k1 + 3u;
    TFR(17); TFR(29); TFR(16); TFR(24);
    x0 += k1;  x1 += ks2 + 4u;
    TFR(13); TFR(15); TFR(26); TFR(6);
    x0 += ks2; x1 += k0 + 5u;
#undef TFR
    o0 = x0; o1 = x1;
}

__device__ __forceinline__ uint32_t rbits32(uint32_t k0, uint32_t k1, uint32_t i) {
    uint32_t a, b;
    tf2x32(k0, k1, 0u, i, a, b);
    return a ^ b;
}

__device__ __forceinline__ float u01(uint32_t bits) {
    return __uint_as_float((bits >> 9) | 0x3f800000u) - 1.0f;
}

__device__ __forceinline__ uint32_t score_key(float f) {
    uint32_t b = __float_as_uint(f);
    return (b & 0x80000000u) ? ~b : (b | 0x80000000u);
}

// ---------------- software grid barrier (all blocks co-resident by construction) ----
__device__ __forceinline__ void gbar() {
    __syncthreads();
    if (threadIdx.x == 0) {
        unsigned gen = g_bar_gen;
        __threadfence();
        if (atomicAdd(&g_bar_count, 1) == (int)gridDim.x - 1) {
            g_bar_count = 0;
            __threadfence();
            g_bar_gen = gen + 1;
        } else {
            while (g_bar_gen == gen) __nanosleep(64);
            __threadfence();
        }
    }
    __syncthreads();
}

// 8-wide broadcast gather macro body (shared by steps and score)
#define GATHER_LOOP(EMB_LOAD)                                                     \
    int tot = min(32, e - base);                                                  \
    int t2 = 0;                                                                   \
    for (; t2 + 8 <= tot; t2 += 8) {                                              \
        int   cA[8]; float vA[8];                                                 \
        _Pragma("unroll")                                                         \
        for (int u = 0; u < 8; u++) {                                             \
            cA[u] = __shfl_sync(0xffffffffu, c, t2 + u);                          \
            vA[u] = __shfl_sync(0xffffffffu, v, t2 + u);                          \
        }                                                                         \
        float fA[8];                                                              \
        _Pragma("unroll")                                                         \
        for (int u = 0; u < 8; u++) fA[u] = EMB_LOAD(cA[u]);                      \
        acc0 += vA[0] * fA[0]; acc1 += vA[1] * fA[1];                             \
        acc2 += vA[2] * fA[2]; acc3 += vA[3] * fA[3];                             \
        acc0 += vA[4] * fA[4]; acc1 += vA[5] * fA[5];                             \
        acc2 += vA[6] * fA[6]; acc3 += vA[7] * fA[7];                             \
    }                                                                             \
    for (; t2 < tot; t2++) {                                                      \
        int   cc = __shfl_sync(0xffffffffu, c, t2);                               \
        float vv = __shfl_sync(0xffffffffu, v, t2);                               \
        acc0 += vv * EMB_LOAD(cc);                                                \
    }

// ---------------- propagation step (STEP = 0,1,2), warp-per-row grid-stride -------
template <int STEP>
__device__ void do_step(int gwarp, int nwarps, int lane, const float* embeds,
                        uint32_t k0, uint32_t k1, uint32_t keep_thresh) {
    const float* emb_cur = (STEP == 0) ? embeds : (STEP == 1) ? g_e0 : g_e1;
    float*       emb_next = (STEP == 0) ? g_e0 : (STEP == 1) ? g_e1 : g_e2;
    const float* num_cur = (STEP == 1) ? g_n0 : g_n1;   // unused for STEP==0
    float*       num_next = (STEP == 0) ? g_n0 : (STEP == 1) ? g_n1 : g_n2;

    for (int r = gwarp; r < NN; r += nwarps) {
        int s = __ldcg(&g_rowptr[r]);
        int deg = (STEP == 0) ? (__ldcg(&g_rowptr[r + 1]) - s) : g_deg[r];
        int e = s + deg;
        float acc0 = 0.f, acc1 = 0.f, acc2 = 0.f, acc3 = 0.f;
        float accn_l = 0.f, acco_l = 0.f;
        int cnt = 0;

        for (int base = s; base < e; base += 32) {
            int j = base + lane;
            bool valid = j < e;
            int4 q = valid ? g_cve[j] : make_int4(0, 0, 0, 0);
            int   c = q.x;
            float v = __int_as_float(q.y);

            if (STEP > 0) { if (valid) accn_l += v * num_cur[c]; }
            acco_l += v;

            // keep <=> u01(bits)+p >= 1 <=> (bits>>9) >= (1-p)*2^23  (exact)
            bool keep = false;
            if (valid && v != 0.f)
                keep = (rbits32(k0, k1, (uint32_t)q.z) >> 9) >= keep_thresh;
            unsigned kb = __ballot_sync(0xffffffffu, keep);   // sync: chunk loads consumed
            int pref = __popc(kb & ((1u << lane) - 1));
            if (keep) g_cve[s + cnt + pref] = q;
            cnt += __popc(kb);

#define LOADE(ci) ((STEP == 0) ? __ldg(&emb_cur[(ci) * DD + lane]) : emb_cur[(ci) * DD + lane])
            GATHER_LOOP(LOADE)
#undef LOADE
        }
        float acc = (acc0 + acc1) + (acc2 + acc3);   // fixed deterministic grouping
#pragma unroll
        for (int o = 16; o; o >>= 1) {
            acco_l += __shfl_xor_sync(0xffffffffu, acco_l, o);
            if (STEP > 0) accn_l += __shfl_xor_sync(0xffffffffu, accn_l, o);
        }

        float ec = (STEP == 0) ? __ldg(&emb_cur[r * DD + lane]) : emb_cur[r * DD + lane];
        if (STEP == 0) {
            emb_next[r * DD + lane] = acc - ec;
            if (lane == 0) { num_next[r] = acco_l; g_order[r] = acco_l; g_deg[r] = cnt; }
        } else {
            float od = g_order[r];
            emb_next[r * DD + lane] = acc - ec - od * ec;
            if (lane == 0) {
                num_next[r] = accn_l - num_cur[r] - od;
                g_order[r] = acco_l;
                g_deg[r] = cnt;
            }
        }
    }
}

// ---------------- THE kernel: everything in one launch ----------------
__global__ void __launch_bounds__(TPB, 8)
mega_kernel(const int* __restrict__ rows, const int* __restrict__ cols,
            const float* __restrict__ adj, const float* __restrict__ embeds,
            float* out, int out_size, int n_score_out,
            uint32_t a0, uint32_t a1, uint32_t b0, uint32_t b1,
            uint32_t c0, uint32_t c1) {
    __shared__ unsigned long long sm_sort[CAP];   // 16KB; reused as int scratch
    __shared__ int sm_small[16];
    int* sm_i = (int*)sm_sort;                    // 4096 ints

    const int B = gridDim.x, t = threadIdx.x, bb = blockIdx.x;
    const int gtid = bb * TPB + t, nthreads = B * TPB;
    const int lane = t & 31;
    const int gwarp = gtid >> 5, nwarps = nthreads >> 5;

    // ---- A: zero counters ----
    for (int i = gtid; i < HSIZE; i += nthreads) g_hist[i] = 0;
    for (int i = gtid; i < NN; i += nthreads) g_rowcnt[i] = 0;
    if (gtid == 0) g_cand_cnt = 0;
    gbar();

    // ---- B: row counts ----
    for (int e = gtid; e < EE; e += nthreads) atomicAdd(&g_rowcnt[__ldg(&rows[e])], 1);
    gbar();

    // ---- C1: per-thread chunk sums + block scan ----
    const int CH = (NN + nthreads - 1) / nthreads;
    const int c_lo = min(gtid * CH, NN), c_hi = min(c_lo + CH, NN);
    int csum = 0;
    for (int i = c_lo; i < c_hi; i++) csum += __ldcg(&g_rowcnt[i]);
    int x = csum;
#pragma unroll
    for (int o = 1; o < 32; o <<= 1) { int y = __shfl_up_sync(0xffffffffu, x, o); if (lane >= o) x += y; }
    if (lane == 31) sm_small[t >> 5] = x;
    __syncthreads();
    if (t == 0) { int run = 0; for (int i = 0; i < 8; i++) { int v = sm_small[i]; sm_small[i] = run; run += v; } sm_small[8] = run; }
    __syncthreads();
    const int excl_in_blk = (x - csum) + sm_small[t >> 5];
    if (t == 0) g_blockTot[bb] = sm_small[8];
    gbar();

    // ---- C2: block 0 scans block totals ----
    if (bb == 0) {
        int CHB = (B + TPB - 1) / TPB;
        int lo = min(t * CHB, B), hi = min(lo + CHB, B);
        int s2 = 0;
        for (int i = lo; i < hi; i++) s2 += __ldcg(&g_blockTot[i]);
        int x2 = s2;
#pragma unroll
        for (int o = 1; o < 32; o <<= 1) { int y = __shfl_up_sync(0xffffffffu, x2, o); if (lane >= o) x2 += y; }
        if (lane == 31) sm_small[t >> 5] = x2;
        __syncthreads();
        if (t == 0) { int run = 0; for (int i = 0; i < 8; i++) { int v = sm_small[i]; sm_small[i] = run; run += v; } }
        __syncthreads();
        int run = (x2 - s2) + sm_small[t >> 5];
        for (int i = lo; i < hi; i++) { g_blockOff[i] = run; run += __ldcg(&g_blockTot[i]); }
    }
    gbar();

    // ---- C3: write rowptr + cursor ----
    {
        int run = __ldcg(&g_blockOff[bb]) + excl_in_blk;
        for (int i = c_lo; i < c_hi; i++) {
            g_rowptr[i] = run;
            g_cursor[i] = run;
            run += __ldcg(&g_rowcnt[i]);
        }
        if (gtid == 0) g_rowptr[NN] = EE;
    }
    gbar();

    // ---- D: scatter edge ids into rows ----
    for (int e = gtid; e < EE; e += nthreads) {
        int pos = atomicAdd(&g_cursor[__ldg(&rows[e])], 1);
        g_perm[pos] = e;
    }
    gbar();

    // ---- E: warp-per-row sort (deterministic order) + pack (col, adj, eid) ----
    for (int r = gwarp; r < NN; r += nwarps) {
        int s = __ldcg(&g_rowptr[r]), e = __ldcg(&g_rowptr[r + 1]);
        int deg = e - s;
        if (deg == 0) continue;
        if (deg <= 32) {
            int v = (lane < deg) ? g_perm[s + lane] : 0x7fffffff;
#pragma unroll
            for (int k = 2; k <= 32; k <<= 1) {
#pragma unroll
                for (int j = k >> 1; j > 0; j >>= 1) {
                    int o = __shfl_xor_sync(0xffffffffu, v, j);
                    bool dir = ((lane & k) == 0);
                    bool lower = ((lane & j) == 0);
                    int mn = min(v, o), mx = max(v, o);
                    v = (dir == lower) ? mn : mx;
                }
            }
            if (lane < deg) {
                int   c = __ldg(&cols[v]);
                float a = __ldg(&adj[v]);
                g_cve[s + lane] = make_int4(c, __float_as_int(a), v, 0);
            }
        } else {
            if (lane == 0) {
                for (int i = s + 1; i < e; i++) {
                    int v = g_perm[i];
                    int j = i - 1;
                    while (j >= s && g_perm[j] > v) { g_perm[j + 1] = g_perm[j]; j--; }
                    g_perm[j + 1] = v;
                }
            }
            __syncwarp();
            for (int j = s + lane; j < e; j += 32) {
                int eid = g_perm[j];
                g_cve[j] = make_int4(__ldg(&cols[eid]), __float_as_int(__ldg(&adj[eid])), eid, 0);
            }
        }
    }
    gbar();

    // ---- F/G/H: propagation steps 0..2 (keep thresholds: (1-p)*2^23) ----
    do_step<0>(gwarp, nwarps, lane, embeds, a0, a1, 0x400000u);
    gbar();
    do_step<1>(gwarp, nwarps, lane, embeds, b0, b1, 0x600000u);
    gbar();
    do_step<2>(gwarp, nwarps, lane, embeds, c0, c1, 0x700000u);
    gbar();

    // ---- I: final step (depth 3) fused with scoring + histogram ----
    for (int r = gwarp; r < NN; r += nwarps) {
        int s = __ldcg(&g_rowptr[r]);
        int e = s + g_deg[r];
        float acc0 = 0.f, acc1 = 0.f, acc2 = 0.f, acc3 = 0.f, accn_l = 0.f;

        for (int base = s; base < e; base += 32) {
            int j = base + lane;
            bool valid = j < e;
            int4 q = valid ? g_cve[j] : make_int4(0, 0, 0, 0);
            int   c = q.x;
            float v = __int_as_float(q.y);
            if (valid) accn_l += v * g_n2[c];
#define LOADE2(ci) (g_e2[(ci) * DD + lane])
            GATHER_LOOP(LOADE2)
#undef LOADE2
        }
        float acc = (acc0 + acc1) + (acc2 + acc3);
#pragma unroll
        for (int o = 16; o; o >>= 1) accn_l += __shfl_xor_sync(0xffffffffu, accn_l, o);

        int idx = r * DD + lane;
        float ec = g_e2[idx];
        float od = g_order[r];
        float en3 = acc - ec - od * ec;
        float n2r = g_n2[r];
        float n3 = accn_l - n2r - od;

        float esum = g_e0[idx] + g_e1[idx] + ec + en3;
        float ns = g_n0[r] + g_n1[r] + n2r + n3 + 1e-8f;
        float sub = esum / ns;
        float em = __ldg(&embeds[idx]);
        float ss = sub * sub, ee2 = em * em;
#pragma unroll
        for (int o = 16; o; o >>= 1) {
            ss += __shfl_xor_sync(0xffffffffu, ss, o);
            ee2 += __shfl_xor_sync(0xffffffffu, ee2, o);
        }
        float na = sub / fmaxf(sqrtf(ss), 1e-12f);
        float nb = em / fmaxf(sqrtf(ee2), 1e-12f);
        float d = na * nb;
#pragma unroll
        for (int o = 16; o; o >>= 1) d += __shfl_xor_sync(0xffffffffu, d, o);

        if (lane == 0) {
            float u = u01(rbits32(0u, 7u, (uint32_t)r));   // key(7)
            float sc = d + (-logf(-logf(u)));
            g_scores[r] = sc;
            if (r < n_score_out) out[r] = sc;
            atomicAdd(&g_hist[score_key(sc) >> (32 - HBITS)], 1);
        }
    }
    gbar();

    // ---- J1: warp-per-chunk hist partial sums (1024 chunks x 128 bins) ----
    for (int c = gwarp; c < 1024; c += nwarps) {
        int sum = 0;
#pragma unroll
        for (int k = 0; k < 4; k++) sum += __ldcg(&g_hist[c * 128 + k * 32 + lane]);
#pragma unroll
        for (int o = 16; o; o >>= 1) sum += __shfl_xor_sync(0xffffffffu, sum, o);
        if (lane == 0) g_chunkSum[c] = sum;
    }
    gbar();

    // ---- J2: block 0 finds threshold digit ----
    if (bb == 0) {
        for (int i = t; i < 1024; i += TPB) sm_i[i] = __ldcg(&g_chunkSum[i]);
        if (t == 0) sm_small[9] = -1;
        __syncthreads();
        int ps = sm_i[t * 4] + sm_i[t * 4 + 1] + sm_i[t * 4 + 2] + sm_i[t * 4 + 3];
        int x2 = ps;
#pragma unroll
        for (int o = 1; o < 32; o <<= 1) { int y = __shfl_up_sync(0xffffffffu, x2, o); if (lane >= o) x2 += y; }
        if (lane == 31) sm_small[t >> 5] = x2;
        __syncthreads();
        if (t == 0) { int run = 0; for (int i = 0; i < 8; i++) { int v = sm_small[i]; sm_small[i] = run; run += v; } sm_small[8] = run; }
        __syncthreads();
        int inclP = x2 + sm_small[t >> 5];
        int total = sm_small[8];
        int suffixGroup = total - (inclP - ps);   // sum of chunks >= t*4
        {
            int run = suffixGroup;
            for (int i = 0; i < 4; i++) {
                int c = t * 4 + i;
                if (run >= KTOP) atomicMax(&sm_small[9], c);
                run -= sm_i[c];
            }
        }
        __syncthreads();
        int cc = sm_small[9];
        {
            int run = suffixGroup;
            for (int i = 0; i < 4; i++) {
                int c = t * 4 + i;
                if (c == cc) sm_small[10] = run;   // S[cc] = sum of chunks >= cc
                run -= sm_i[c];
            }
        }
        __syncthreads();
        int ccv = sm_i[cc];                        // read BEFORE overwriting scratch
        __syncthreads();
        if (t < 128) sm_i[1024 + t] = __ldcg(&g_hist[cc * 128 + t]);
        __syncthreads();
        if (t == 0) {
            int cum = sm_small[10] - ccv;          // everything strictly above chunk cc
            int digit = cc * 128;
            for (int bbin = 127; bbin >= 0; bbin--) {
                int h = sm_i[1024 + bbin];
                if (cum + h >= KTOP) { digit = cc * 128 + bbin; break; }
                cum += h;
            }
            g_sel_digit = digit;
        }
    }
    gbar();

    // ---- K: compact candidates ----
    {
        int sd = __ldcg(&g_sel_digit);
        for (int i = gtid; i < NN; i += nthreads) {
            uint32_t k = score_key(__ldcg(&g_scores[i]));
            if ((int)(k >> (32 - HBITS)) >= sd) {
                int p = atomicAdd(&g_cand_cnt, 1);
                if (p < CAP) { g_cand_key[p] = k; g_cand_idx[p] = i; }
            }
        }
    }
    gbar();

    // ---- L: block 0 sorts candidates (bitonic) and writes top-k ----
    if (bb == 0) {
        int n = __ldcg(&g_cand_cnt); if (n > CAP) n = CAP;
        int m = KTOP; while (m < n) m <<= 1;
        for (int i = t; i < m; i += TPB) {
            sm_sort[i] = (i < n)
                ? ((((unsigned long long)__ldcg(&g_cand_key[i])) << 32) |
                   (uint32_t)(~(uint32_t)__ldcg(&g_cand_idx[i])))
                : 0ull;
        }
        __syncthreads();
        for (int size = 2; size <= m; size <<= 1) {
            for (int stride = size >> 1; stride > 0; stride >>= 1) {
                for (int i = t; i < m / 2; i += TPB) {
                    int lo = 2 * i - (i & (stride - 1));
                    int hi = lo + stride;
                    bool desc = ((lo & size) == 0);
                    unsigned long long a = sm_sort[lo], b2 = sm_sort[hi];
                    bool sw = desc ? (a < b2) : (a > b2);
                    if (sw) { sm_sort[lo] = b2; sm_sort[hi] = a; }
                }
                __syncthreads();
            }
        }
        for (int j = t; j < KTOP; j += TPB) {
            uint32_t idx = ~(uint32_t)(sm_sort[j] & 0xffffffffull);
            if (out_size >= NN + KTOP) out[NN + j] = (float)idx;
            else if (out_size == KTOP) ((int*)out)[j] = (int)idx;
        }
    }
}

// ---------------- launch ----------------
extern "C" void kernel_launch(void* const* d_in, const int* in_sizes, int n_in,
                              void* d_out, int out_size) {
    const int* rows = (const int*)d_in[0];       // edge_index[0]
    const int* cols = rows + EE;                 // edge_index[1]
    const float* adj = (const float*)d_in[1];
    const float* embeds = (const float*)d_in[2];
    float* out = (float*)d_out;
    (void)in_sizes; (void)n_in;

    // fold_in(key(42), i): threefry((0,42),(0,i)) -> derived key
    uint32_t fk[3][2];
    for (uint32_t i = 0; i < 3; i++) tf2x32(0u, 42u, 0u, i, fk[i][0], fk[i][1]);

    // grid sized for guaranteed co-residency (software grid barrier)
    int dev = 0; cudaGetDevice(&dev);
    int nsm = 0; cudaDeviceGetAttribute(&nsm, cudaDevAttrMultiProcessorCount, dev);
    int bpm = 0;
    cudaOccupancyMaxActiveBlocksPerMultiprocessor(&bpm, mega_kernel, TPB, 0);
    int B = nsm * bpm;
    if (B < 1) B = 1;
    if (B > 2048) B = 2048;

    int n_score_out = (out_size == KTOP) ? 0 : ((out_size < NN) ? out_size : NN);
    mega_kernel<<<B, TPB>>>(rows, cols, adj, embeds, out, out_size, n_score_out,
                            fk[0][0], fk[0][1], fk[1][0], fk[1][1], fk[2][0], fk[2][1]);
}